// round 1
// baseline (speedup 1.0000x reference)
#include <cuda_runtime.h>
#include <math.h>

#define MM 2000
#define NB 4096
#define CAND 4096
#define EDGE_MAX 4096

// ---------------- device scratch (no allocations allowed) ----------------
__device__ unsigned int       g_hist[NB];
__device__ unsigned int       g_cutoff;
__device__ int                g_candCount;
__device__ int                g_edgeCount;
__device__ unsigned long long g_cand[CAND];
__device__ float4             g_boxes[MM];
__device__ int                g_keep0[MM];
__device__ unsigned int       g_edges[EDGE_MAX];

// ---------------- k_init: reset per-replay state ----------------
__global__ void k_init() {
    int i = blockIdx.x * blockDim.x + threadIdx.x;
    if (i < NB) g_hist[i] = 0u;
    if (i == 0) { g_cutoff = 0u; g_candCount = 0; g_edgeCount = 0; }
}

// ---------------- k_hist: bucket histogram of fg scores > 0.5 ----------------
// fg in (0.5, 1.0) -> float bits in (0x3F000000, 0x3F800000); monotone.
__global__ void k_hist(const float2* __restrict__ score, int n) {
    __shared__ unsigned int sh[NB];
    for (int i = threadIdx.x; i < NB; i += blockDim.x) sh[i] = 0u;
    __syncthreads();
    int stride = gridDim.x * blockDim.x;
    for (int i = blockIdx.x * blockDim.x + threadIdx.x; i < n; i += stride) {
        float v = score[i].y;
        if (v > 0.5f) {
            unsigned u = __float_as_uint(v);
            unsigned b = (u - 0x3F000000u) >> 11;
            if (b > NB - 1u) b = NB - 1u;
            atomicAdd(&sh[b], 1u);
        }
    }
    __syncthreads();
    for (int i = threadIdx.x; i < NB; i += blockDim.x) {
        unsigned c = sh[i];
        if (c) atomicAdd(&g_hist[i], c);
    }
}

// ---------------- k_scan: find cutoff bucket B: largest b with S(>=b) >= M ----
__global__ void k_scan() {
    __shared__ unsigned h[NB];
    __shared__ unsigned wsum[32];
    int t = threadIdx.x; // 1024 threads
    for (int i = t; i < NB; i += 1024) h[i] = g_hist[i];
    __syncthreads();
    // thread t owns chunk (1023 - t): highest buckets scanned first
    int chunk = 1023 - t;
    unsigned orig = h[chunk * 4 + 0] + h[chunk * 4 + 1] + h[chunk * 4 + 2] + h[chunk * 4 + 3];
    unsigned v = orig;
    int lane = t & 31, wid = t >> 5;
    #pragma unroll
    for (int d = 1; d < 32; d <<= 1) {
        unsigned nv = __shfl_up_sync(0xffffffffu, v, d);
        if (lane >= d) v += nv;
    }
    if (lane == 31) wsum[wid] = v;
    __syncthreads();
    if (wid == 0) {
        unsigned w = wsum[lane];
        #pragma unroll
        for (int d = 1; d < 32; d <<= 1) {
            unsigned nw = __shfl_up_sync(0xffffffffu, w, d);
            if (lane >= d) w += nw;
        }
        wsum[lane] = w;
    }
    __syncthreads();
    unsigned incl = v + (wid ? wsum[wid - 1] : 0u);
    unsigned run = incl - orig;          // count of values in buckets strictly above this chunk
    #pragma unroll
    for (int j = 3; j >= 0; j--) {       // walk chunk from high bucket to low
        int b = chunk * 4 + j;
        unsigned Sb = run + h[b];
        if (Sb >= (unsigned)MM && run < (unsigned)MM) g_cutoff = (unsigned)b;
        run = Sb;
    }
}

// ---------------- k_compact: gather candidate (bits, ~idx) keys ----------------
__global__ void k_compact(const float2* __restrict__ score, int n) {
    unsigned cut = g_cutoff;
    int stride = gridDim.x * blockDim.x;
    for (int i = blockIdx.x * blockDim.x + threadIdx.x; i < n; i += stride) {
        float v = score[i].y;
        if (v > 0.5f) {
            unsigned u = __float_as_uint(v);
            unsigned b = (u - 0x3F000000u) >> 11;
            if (b > NB - 1u) b = NB - 1u;
            if (b >= cut) {
                int pos = atomicAdd(&g_candCount, 1);
                if (pos < CAND)
                    g_cand[pos] = ((unsigned long long)u << 32) | (unsigned long long)(0xFFFFFFFFu - (unsigned)i);
            }
        }
    }
}

// ---------------- k_sort_decode: bitonic sort (desc) + top-M decode ----------------
// key = (score_bits << 32) | (0xFFFFFFFF - idx): desc sort == value desc, idx asc (jax top_k tie rule)
__global__ void k_sort_decode(const float4* __restrict__ anchors,
                              const float4* __restrict__ deltas) {
    __shared__ unsigned long long s[CAND]; // 32 KB
    int t = threadIdx.x; // 1024
    int cnt = g_candCount; if (cnt > CAND) cnt = CAND;
    for (int i = t; i < CAND; i += 1024) s[i] = (i < cnt) ? g_cand[i] : 0ULL;
    __syncthreads();
    for (int k = 2; k <= CAND; k <<= 1) {
        for (int j = k >> 1; j > 0; j >>= 1) {
            for (int i = t; i < CAND; i += 1024) {
                int ixj = i ^ j;
                if (ixj > i) {
                    unsigned long long a = s[i], b = s[ixj];
                    bool up = ((i & k) == 0);
                    if (up ? (a < b) : (a > b)) { s[i] = b; s[ixj] = a; }
                }
            }
            __syncthreads();
        }
    }
    // decode boxes exactly like reference
    for (int m = t; m < MM; m += 1024) {
        unsigned long long key = s[m];
        bool valid = (key >> 32) != 0ULL;
        unsigned idx = 0xFFFFFFFFu - (unsigned)(key & 0xFFFFFFFFull);
        float4 a = valid ? anchors[idx] : make_float4(0.f, 0.f, 0.f, 0.f);
        float4 d = valid ? deltas[idx]  : make_float4(0.f, 0.f, 0.f, 0.f);
        float w  = a.z - a.x;
        float h  = a.w - a.y;
        float cx = a.x + 0.5f * w;
        float cy = a.y + 0.5f * h;
        float ncx = cx + d.x * w;
        float ncy = cy + d.y * h;
        float nw  = w * expf(d.z);
        float nh  = h * expf(d.w);
        float x1 = ncx - 0.5f * nw, y1 = ncy - 0.5f * nh;
        float x2 = ncx + 0.5f * nw, y2 = ncy + 0.5f * nh;
        x1 = fminf(fmaxf(x1, 0.f), 1024.f);
        y1 = fminf(fmaxf(y1, 0.f), 1024.f);
        x2 = fminf(fmaxf(x2, 0.f), 1024.f);
        y2 = fminf(fmaxf(y2, 0.f), 1024.f);
        bool big = ((x2 - x1) >= 1.0f) && ((y2 - y1) >= 1.0f);
        g_boxes[m] = make_float4(x1, y1, x2, y2);
        g_keep0[m] = (valid && big) ? 1 : 0;
    }
}

// ---------------- k_pairs: upper-triangle IoU > 0.7 -> edge list ----------------
#define TB 64
__global__ void k_pairs() {
    int bx = blockIdx.x, by = blockIdx.y; // i-tile, j-tile
    if (by < bx) return;
    __shared__ float4 bi[TB], bj[TB];
    __shared__ float  ai[TB], aj[TB];
    __shared__ int    ki[TB], kj[TB];
    int t = threadIdx.x; // 256
    if (t < TB) {
        int i = bx * TB + t;
        if (i < MM) { float4 b = g_boxes[i]; bi[t] = b; ai[t] = (b.z - b.x) * (b.w - b.y); ki[t] = g_keep0[i]; }
        else ki[t] = 0;
        int j = by * TB + t;
        if (j < MM) { float4 b = g_boxes[j]; bj[t] = b; aj[t] = (b.z - b.x) * (b.w - b.y); kj[t] = g_keep0[j]; }
        else kj[t] = 0;
    }
    __syncthreads();
    for (int p = t; p < TB * TB; p += 256) {
        int li = p >> 6, lj = p & 63;
        int i = bx * TB + li, j = by * TB + lj;
        if (j <= i || j >= MM) continue;
        if (!ki[li] || !kj[lj]) continue;
        float4 A = bi[li], B = bj[lj];
        float ltx = fmaxf(A.x, B.x), lty = fmaxf(A.y, B.y);
        float rbx = fminf(A.z, B.z), rby = fminf(A.w, B.w);
        float iw = fmaxf(rbx - ltx, 0.f), ih = fmaxf(rby - lty, 0.f);
        float inter = iw * ih;
        float iou = inter / (ai[li] + aj[lj] - inter + 1e-9f);
        if (iou > 0.7f) {
            int pos = atomicAdd(&g_edgeCount, 1);
            if (pos < EDGE_MAX) g_edges[pos] = ((unsigned)i << 16) | (unsigned)j;
        }
    }
}

// ---------------- k_finalize: order edges, resolve greedy NMS, write out ----------------
__global__ void k_finalize(float* __restrict__ out) {
    __shared__ unsigned char dead[MM];
    __shared__ unsigned se[EDGE_MAX]; // 16 KB
    int t = threadIdx.x; // 1024
    for (int m = t; m < MM; m += 1024) dead[m] = g_keep0[m] ? 0 : 1;
    int ec = g_edgeCount; if (ec > EDGE_MAX) ec = EDGE_MAX;
    for (int i = t; i < EDGE_MAX; i += 1024) se[i] = (i < ec) ? g_edges[i] : 0xFFFFFFFFu;
    __syncthreads();

    if (ec > 256) {
        // bitonic ascending: packed (i<<16|j) sorts by i then j
        for (int k = 2; k <= EDGE_MAX; k <<= 1) {
            for (int j = k >> 1; j > 0; j >>= 1) {
                for (int i = t; i < EDGE_MAX; i += 1024) {
                    int ixj = i ^ j;
                    if (ixj > i) {
                        unsigned a = se[i], b = se[ixj];
                        bool up = ((i & k) == 0);
                        if (up ? (a > b) : (a < b)) { se[i] = b; se[ixj] = a; }
                    }
                }
                __syncthreads();
            }
        }
    } else if (t == 0) {
        // tiny edge set: insertion sort
        for (int a = 1; a < ec; a++) {
            unsigned key = se[a];
            int b = a - 1;
            while (b >= 0 && se[b] > key) { se[b + 1] = se[b]; b--; }
            se[b + 1] = key;
        }
    }
    __syncthreads();

    if (t == 0) {
        // greedy NMS: edges sorted by suppressor index; suppressor must itself be alive
        for (int e = 0; e < ec; e++) {
            unsigned u = se[e];
            int i = (int)(u >> 16), j = (int)(u & 0xFFFFu);
            if (!dead[i]) dead[j] = 1;
        }
    }
    __syncthreads();

    for (int m = t; m < MM; m += 1024) {
        bool keep = (dead[m] == 0);
        float4 b = g_boxes[m];
        out[m * 4 + 0] = keep ? b.x : 0.f;
        out[m * 4 + 1] = keep ? b.y : 0.f;
        out[m * 4 + 2] = keep ? b.z : 0.f;
        out[m * 4 + 3] = keep ? b.w : 0.f;
        out[MM * 4 + m] = keep ? 1.f : 0.f;
    }
}

// ---------------- launch ----------------
extern "C" void kernel_launch(void* const* d_in, const int* in_sizes, int n_in,
                              void* d_out, int out_size) {
    // identify score as the smallest input (N,2); others in order: anchors, box_regression
    int si = 0;
    for (int i = 1; i < n_in; i++) if (in_sizes[i] < in_sizes[si]) si = i;
    int others[2], o = 0;
    for (int i = 0; i < n_in && o < 2; i++) if (i != si) others[o++] = i;

    const float4* anchors = (const float4*)d_in[others[0]];
    const float2* score   = (const float2*)d_in[si];
    const float4* deltas  = (const float4*)d_in[others[1]];
    int n = in_sizes[si] / 2;

    k_init<<<(NB + 255) / 256, 256>>>();
    k_hist<<<128, 1024>>>(score, n);
    k_scan<<<1, 1024>>>();
    k_compact<<<256, 1024>>>(score, n);
    k_sort_decode<<<1, 1024>>>(anchors, deltas);
    dim3 pg((MM + TB - 1) / TB, (MM + TB - 1) / TB);
    k_pairs<<<pg, 256>>>();
    k_finalize<<<1, 1024>>>((float*)d_out);
}

// round 2
// speedup vs baseline: 1.0656x; 1.0656x over previous
#include <cuda_runtime.h>
#include <math.h>

#define MM 2000
#define NB 4096
#define CAND 4096
#define EDGE_MAX 4096
#define T_STATIC 0.99925f

// ---------------- device scratch (zero-initialized at module load) ----------------
__device__ unsigned int       g_hist[NB];
__device__ unsigned int       g_cutoff;
__device__ int                g_candCount;
__device__ int                g_edgeCount;
__device__ int                g_fb;
__device__ unsigned long long g_cand[CAND];
__device__ float4             g_boxes[MM];
__device__ int                g_keep0[MM];
__device__ unsigned int       g_edges[EDGE_MAX];

// ---------------- helpers ----------------
__device__ __forceinline__ void proc_spec(unsigned* sh, float v, unsigned idx) {
    if (v > 0.5f) {
        unsigned u = __float_as_uint(v);
        unsigned b = (u - 0x3F000000u) >> 11;
        if (b > NB - 1u) b = NB - 1u;
        atomicAdd(&sh[b], 1u);
        if (v > T_STATIC) {
            int pos = atomicAdd(&g_candCount, 1);
            if (pos < CAND)
                g_cand[pos] = ((unsigned long long)u << 32) |
                              (unsigned long long)(0xFFFFFFFFu - idx);
        }
    }
}

// ---------------- k_main: ONE 32MB pass — partial hist + speculative compact ----
__global__ __launch_bounds__(1024) void k_main(const float4* __restrict__ s4, int n4) {
    __shared__ unsigned sh[NB];
    for (int i = threadIdx.x; i < NB; i += 1024) sh[i] = 0u;
    __syncthreads();
    int nthr = gridDim.x * blockDim.x;
    int tid  = blockIdx.x * blockDim.x + threadIdx.x;
    for (int i = tid; i < n4; i += 4 * nthr) {
        int i1 = i + nthr, i2 = i + 2 * nthr, i3 = i + 3 * nthr;
        bool b1 = i1 < n4, b2 = i2 < n4, b3 = i3 < n4;
        float4 a0 = __ldg(s4 + i);
        float4 a1, a2, a3;
        if (b1) a1 = __ldg(s4 + i1);
        if (b2) a2 = __ldg(s4 + i2);
        if (b3) a3 = __ldg(s4 + i3);
        // float4 covers two (bg,fg) pairs: .y = fg[2i], .w = fg[2i+1]
        proc_spec(sh, a0.y, 2u * (unsigned)i);
        proc_spec(sh, a0.w, 2u * (unsigned)i + 1u);
        if (b1) { proc_spec(sh, a1.y, 2u * (unsigned)i1); proc_spec(sh, a1.w, 2u * (unsigned)i1 + 1u); }
        if (b2) { proc_spec(sh, a2.y, 2u * (unsigned)i2); proc_spec(sh, a2.w, 2u * (unsigned)i2 + 1u); }
        if (b3) { proc_spec(sh, a3.y, 2u * (unsigned)i3); proc_spec(sh, a3.w, 2u * (unsigned)i3 + 1u); }
    }
    __syncthreads();
    for (int i = threadIdx.x; i < NB; i += 1024) {
        unsigned c = sh[i];
        if (c) atomicAdd(&g_hist[i], c);
    }
}

// ---------------- k_scan: cutoff bucket + fallback flag; re-zeroes hist ----------
__global__ void k_scan() {
    __shared__ unsigned h[NB];
    __shared__ unsigned wsum[32];
    int t = threadIdx.x; // 1024 threads
    for (int i = t; i < NB; i += 1024) { h[i] = g_hist[i]; g_hist[i] = 0u; }
    __syncthreads();
    // thread t owns chunk (1023 - t): highest buckets scanned first
    int chunk = 1023 - t;
    unsigned orig = h[chunk * 4 + 0] + h[chunk * 4 + 1] + h[chunk * 4 + 2] + h[chunk * 4 + 3];
    unsigned v = orig;
    int lane = t & 31, wid = t >> 5;
    #pragma unroll
    for (int d = 1; d < 32; d <<= 1) {
        unsigned nv = __shfl_up_sync(0xffffffffu, v, d);
        if (lane >= d) v += nv;
    }
    if (lane == 31) wsum[wid] = v;
    __syncthreads();
    if (wid == 0) {
        unsigned w = wsum[lane];
        #pragma unroll
        for (int d = 1; d < 32; d <<= 1) {
            unsigned nw = __shfl_up_sync(0xffffffffu, w, d);
            if (lane >= d) w += nw;
        }
        wsum[lane] = w;
    }
    __syncthreads();
    unsigned incl = v + (wid ? wsum[wid - 1] : 0u);
    unsigned run = incl - orig; // count strictly above this chunk
    #pragma unroll
    for (int j = 3; j >= 0; j--) {
        int b = chunk * 4 + j;
        unsigned Sb = run + h[b];
        if (Sb >= (unsigned)MM && run < (unsigned)MM) g_cutoff = (unsigned)b;
        run = Sb;
    }
    if (t == 0) {
        int c = g_candCount;
        int fb = (c < MM || c > CAND) ? 1 : 0;
        g_fb = fb;
        if (fb) g_candCount = 0;   // fallback recompacts from scratch
        g_edgeCount = 0;
    }
}

// ---------------- k_fb: fallback exact-cutoff compact (usually early-exits) ------
__global__ void k_fb(const float2* __restrict__ score, int n) {
    if (!g_fb) return;
    unsigned cut = g_cutoff;
    int stride = gridDim.x * blockDim.x;
    for (int i = blockIdx.x * blockDim.x + threadIdx.x; i < n; i += stride) {
        float v = score[i].y;
        if (v > 0.5f) {
            unsigned u = __float_as_uint(v);
            unsigned b = (u - 0x3F000000u) >> 11;
            if (b > NB - 1u) b = NB - 1u;
            if (b >= cut) {
                int pos = atomicAdd(&g_candCount, 1);
                if (pos < CAND)
                    g_cand[pos] = ((unsigned long long)u << 32) |
                                  (unsigned long long)(0xFFFFFFFFu - (unsigned)i);
            }
        }
    }
}

// ---------------- k_sort_decode: bitonic desc sort + top-M box decode ------------
__global__ void k_sort_decode(const float4* __restrict__ anchors,
                              const float4* __restrict__ deltas) {
    __shared__ unsigned long long s[CAND]; // 32 KB
    int t = threadIdx.x; // 1024
    int cnt = g_candCount; if (cnt > CAND) cnt = CAND;
    for (int i = t; i < CAND; i += 1024) s[i] = (i < cnt) ? g_cand[i] : 0ULL;
    __syncthreads();
    if (t == 0) g_candCount = 0;   // reset for next replay
    for (int k = 2; k <= CAND; k <<= 1) {
        for (int j = k >> 1; j > 0; j >>= 1) {
            for (int i = t; i < CAND; i += 1024) {
                int ixj = i ^ j;
                if (ixj > i) {
                    unsigned long long a = s[i], b = s[ixj];
                    bool up = ((i & k) == 0);
                    if (up ? (a < b) : (a > b)) { s[i] = b; s[ixj] = a; }
                }
            }
            __syncthreads();
        }
    }
    for (int m = t; m < MM; m += 1024) {
        unsigned long long key = s[m];
        bool valid = (key >> 32) != 0ULL;
        unsigned idx = 0xFFFFFFFFu - (unsigned)(key & 0xFFFFFFFFull);
        float4 a = valid ? __ldg(anchors + idx) : make_float4(0.f, 0.f, 0.f, 0.f);
        float4 d = valid ? __ldg(deltas + idx)  : make_float4(0.f, 0.f, 0.f, 0.f);
        float w  = a.z - a.x;
        float h  = a.w - a.y;
        float cx = a.x + 0.5f * w;
        float cy = a.y + 0.5f * h;
        float ncx = cx + d.x * w;
        float ncy = cy + d.y * h;
        float nw  = w * expf(d.z);
        float nh  = h * expf(d.w);
        float x1 = ncx - 0.5f * nw, y1 = ncy - 0.5f * nh;
        float x2 = ncx + 0.5f * nw, y2 = ncy + 0.5f * nh;
        x1 = fminf(fmaxf(x1, 0.f), 1024.f);
        y1 = fminf(fmaxf(y1, 0.f), 1024.f);
        x2 = fminf(fmaxf(x2, 0.f), 1024.f);
        y2 = fminf(fmaxf(y2, 0.f), 1024.f);
        bool big = ((x2 - x1) >= 1.0f) && ((y2 - y1) >= 1.0f);
        g_boxes[m] = make_float4(x1, y1, x2, y2);
        g_keep0[m] = (valid && big) ? 1 : 0;
    }
}

// ---------------- k_pairs: upper-triangle IoU > 0.7 -> edge list -----------------
#define TB 64
__global__ void k_pairs() {
    int bx = blockIdx.x, by = blockIdx.y;
    if (by < bx) return;
    __shared__ float4 bi[TB], bj[TB];
    __shared__ float  ai[TB], aj[TB];
    __shared__ int    ki[TB], kj[TB];
    int t = threadIdx.x; // 256
    if (t < TB) {
        int i = bx * TB + t;
        if (i < MM) { float4 b = g_boxes[i]; bi[t] = b; ai[t] = (b.z - b.x) * (b.w - b.y); ki[t] = g_keep0[i]; }
        else ki[t] = 0;
        int j = by * TB + t;
        if (j < MM) { float4 b = g_boxes[j]; bj[t] = b; aj[t] = (b.z - b.x) * (b.w - b.y); kj[t] = g_keep0[j]; }
        else kj[t] = 0;
    }
    __syncthreads();
    for (int p = t; p < TB * TB; p += 256) {
        int li = p >> 6, lj = p & 63;
        int i = bx * TB + li, j = by * TB + lj;
        if (j <= i || j >= MM) continue;
        if (!ki[li] || !kj[lj]) continue;
        float4 A = bi[li], B = bj[lj];
        float ltx = fmaxf(A.x, B.x), lty = fmaxf(A.y, B.y);
        float rbx = fminf(A.z, B.z), rby = fminf(A.w, B.w);
        float iw = fmaxf(rbx - ltx, 0.f), ih = fmaxf(rby - lty, 0.f);
        float inter = iw * ih;
        float iou = inter / (ai[li] + aj[lj] - inter + 1e-9f);
        if (iou > 0.7f) {
            int pos = atomicAdd(&g_edgeCount, 1);
            if (pos < EDGE_MAX) g_edges[pos] = ((unsigned)i << 16) | (unsigned)j;
        }
    }
}

// ---------------- k_finalize: order edges, resolve greedy NMS, write out ---------
__global__ void k_finalize(float* __restrict__ out) {
    __shared__ unsigned char dead[MM];
    __shared__ unsigned se[EDGE_MAX]; // 16 KB
    int t = threadIdx.x; // 1024
    for (int m = t; m < MM; m += 1024) dead[m] = g_keep0[m] ? 0 : 1;
    int ec = g_edgeCount; if (ec > EDGE_MAX) ec = EDGE_MAX;
    for (int i = t; i < EDGE_MAX; i += 1024) se[i] = (i < ec) ? g_edges[i] : 0xFFFFFFFFu;
    __syncthreads();

    if (ec > 256) {
        for (int k = 2; k <= EDGE_MAX; k <<= 1) {
            for (int j = k >> 1; j > 0; j >>= 1) {
                for (int i = t; i < EDGE_MAX; i += 1024) {
                    int ixj = i ^ j;
                    if (ixj > i) {
                        unsigned a = se[i], b = se[ixj];
                        bool up = ((i & k) == 0);
                        if (up ? (a > b) : (a < b)) { se[i] = b; se[ixj] = a; }
                    }
                }
                __syncthreads();
            }
        }
    } else if (t == 0) {
        for (int a = 1; a < ec; a++) {
            unsigned key = se[a];
            int b = a - 1;
            while (b >= 0 && se[b] > key) { se[b + 1] = se[b]; b--; }
            se[b + 1] = key;
        }
    }
    __syncthreads();

    if (t == 0) {
        for (int e = 0; e < ec; e++) {
            unsigned u = se[e];
            int i = (int)(u >> 16), j = (int)(u & 0xFFFFu);
            if (!dead[i]) dead[j] = 1;
        }
    }
    __syncthreads();

    for (int m = t; m < MM; m += 1024) {
        bool keep = (dead[m] == 0);
        float4 b = g_boxes[m];
        out[m * 4 + 0] = keep ? b.x : 0.f;
        out[m * 4 + 1] = keep ? b.y : 0.f;
        out[m * 4 + 2] = keep ? b.z : 0.f;
        out[m * 4 + 3] = keep ? b.w : 0.f;
        out[MM * 4 + m] = keep ? 1.f : 0.f;
    }
}

// ---------------- launch ----------------
extern "C" void kernel_launch(void* const* d_in, const int* in_sizes, int n_in,
                              void* d_out, int out_size) {
    int si = 0;
    for (int i = 1; i < n_in; i++) if (in_sizes[i] < in_sizes[si]) si = i;
    int others[2], o = 0;
    for (int i = 0; i < n_in && o < 2; i++) if (i != si) others[o++] = i;

    const float4* anchors = (const float4*)d_in[others[0]];
    const float2* score   = (const float2*)d_in[si];
    const float4* deltas  = (const float4*)d_in[others[1]];
    int n  = in_sizes[si] / 2;   // number of (bg,fg) rows
    int n4 = in_sizes[si] / 4;   // number of float4 chunks (2 rows each)

    k_main<<<132, 1024>>>((const float4*)score, n4);
    k_scan<<<1, 1024>>>();
    k_fb<<<132, 256>>>(score, n);
    k_sort_decode<<<1, 1024>>>(anchors, deltas);
    dim3 pg((MM + TB - 1) / TB, (MM + TB - 1) / TB);
    k_pairs<<<pg, 256>>>();
    k_finalize<<<1, 1024>>>((float*)d_out);
}

// round 3
// speedup vs baseline: 1.8830x; 1.7671x over previous
#include <cuda_runtime.h>
#include <math.h>

#define MM 2000
#define NB 4096
#define CAND 4096
#define EDGE_MAX 4096
#define T_STATIC 0.99925f

// ---------------- device scratch (zero-initialized at module load) ----------------
__device__ unsigned int       g_hist[NB];
__device__ unsigned int       g_cutoff;
__device__ int                g_candCount;
__device__ int                g_edgeCount;
__device__ int                g_fb;
__device__ unsigned long long g_cand[CAND];
__device__ unsigned long long g_topKeys[MM];
__device__ float4             g_boxes[MM];
__device__ int                g_keep0[MM];
__device__ unsigned int       g_edges[EDGE_MAX];

// ---------------- helpers ----------------
__device__ __forceinline__ void proc_spec(unsigned* sh, float v, unsigned idx) {
    if (v > 0.5f) {
        unsigned u = __float_as_uint(v);
        unsigned b = (u - 0x3F000000u) >> 11;
        if (b > NB - 1u) b = NB - 1u;
        atomicAdd(&sh[b], 1u);
        if (v > T_STATIC) {
            int pos = atomicAdd(&g_candCount, 1);
            if (pos < CAND)
                g_cand[pos] = ((unsigned long long)u << 32) |
                              (unsigned long long)(0xFFFFFFFFu - idx);
        }
    }
}

// ---------------- k_main: ONE 32MB pass — partial hist + speculative compact ----
__global__ __launch_bounds__(1024) void k_main(const float4* __restrict__ s4, int n4) {
    __shared__ unsigned sh[NB];
    for (int i = threadIdx.x; i < NB; i += 1024) sh[i] = 0u;
    __syncthreads();
    int nthr = gridDim.x * blockDim.x;
    int tid  = blockIdx.x * blockDim.x + threadIdx.x;
    for (int i = tid; i < n4; i += 4 * nthr) {
        int i1 = i + nthr, i2 = i + 2 * nthr, i3 = i + 3 * nthr;
        bool b1 = i1 < n4, b2 = i2 < n4, b3 = i3 < n4;
        float4 a0 = __ldg(s4 + i);
        float4 a1, a2, a3;
        if (b1) a1 = __ldg(s4 + i1);
        if (b2) a2 = __ldg(s4 + i2);
        if (b3) a3 = __ldg(s4 + i3);
        proc_spec(sh, a0.y, 2u * (unsigned)i);
        proc_spec(sh, a0.w, 2u * (unsigned)i + 1u);
        if (b1) { proc_spec(sh, a1.y, 2u * (unsigned)i1); proc_spec(sh, a1.w, 2u * (unsigned)i1 + 1u); }
        if (b2) { proc_spec(sh, a2.y, 2u * (unsigned)i2); proc_spec(sh, a2.w, 2u * (unsigned)i2 + 1u); }
        if (b3) { proc_spec(sh, a3.y, 2u * (unsigned)i3); proc_spec(sh, a3.w, 2u * (unsigned)i3 + 1u); }
    }
    __syncthreads();
    for (int i = threadIdx.x; i < NB; i += 1024) {
        unsigned c = sh[i];
        if (c) atomicAdd(&g_hist[i], c);
    }
}

// ---------------- k_scan: cutoff + fallback flag; re-zero hist + topKeys ---------
__global__ void k_scan() {
    __shared__ unsigned h[NB];
    __shared__ unsigned wsum[32];
    int t = threadIdx.x; // 1024
    for (int i = t; i < NB; i += 1024) { h[i] = g_hist[i]; g_hist[i] = 0u; }
    for (int i = t; i < MM; i += 1024) g_topKeys[i] = 0ULL;
    __syncthreads();
    int chunk = 1023 - t;
    unsigned orig = h[chunk * 4 + 0] + h[chunk * 4 + 1] + h[chunk * 4 + 2] + h[chunk * 4 + 3];
    unsigned v = orig;
    int lane = t & 31, wid = t >> 5;
    #pragma unroll
    for (int d = 1; d < 32; d <<= 1) {
        unsigned nv = __shfl_up_sync(0xffffffffu, v, d);
        if (lane >= d) v += nv;
    }
    if (lane == 31) wsum[wid] = v;
    __syncthreads();
    if (wid == 0) {
        unsigned w = wsum[lane];
        #pragma unroll
        for (int d = 1; d < 32; d <<= 1) {
            unsigned nw = __shfl_up_sync(0xffffffffu, w, d);
            if (lane >= d) w += nw;
        }
        wsum[lane] = w;
    }
    __syncthreads();
    unsigned incl = v + (wid ? wsum[wid - 1] : 0u);
    unsigned run = incl - orig;
    #pragma unroll
    for (int j = 3; j >= 0; j--) {
        int b = chunk * 4 + j;
        unsigned Sb = run + h[b];
        if (Sb >= (unsigned)MM && run < (unsigned)MM) g_cutoff = (unsigned)b;
        run = Sb;
    }
    if (t == 0) {
        int c = g_candCount;
        int fb = (c < MM || c > CAND) ? 1 : 0;
        g_fb = fb;
        if (fb) g_candCount = 0;
        g_edgeCount = 0;
    }
}

// ---------------- k_fb: fallback exact-cutoff compact (usually early-exits) ------
__global__ void k_fb(const float2* __restrict__ score, int n) {
    if (!g_fb) return;
    unsigned cut = g_cutoff;
    int stride = gridDim.x * blockDim.x;
    for (int i = blockIdx.x * blockDim.x + threadIdx.x; i < n; i += stride) {
        float v = score[i].y;
        if (v > 0.5f) {
            unsigned u = __float_as_uint(v);
            unsigned b = (u - 0x3F000000u) >> 11;
            if (b > NB - 1u) b = NB - 1u;
            if (b >= cut) {
                int pos = atomicAdd(&g_candCount, 1);
                if (pos < CAND)
                    g_cand[pos] = ((unsigned long long)u << 32) |
                                  (unsigned long long)(0xFFFFFFFFu - (unsigned)i);
            }
        }
    }
}

// ---------------- k_rank: warp-per-candidate rank-by-count -> scatter sorted -----
// rank(c) = #{keys > key_c}; keys distinct (unique index in low bits).
__global__ __launch_bounds__(1024) void k_rank() {
    __shared__ unsigned long long keys[CAND]; // 32 KB
    int cnt = g_candCount; if (cnt > CAND) cnt = CAND;
    int t = threadIdx.x;
    for (int i = t; i < CAND; i += 1024) keys[i] = (i < cnt) ? g_cand[i] : 0ULL;
    __syncthreads();
    int gw = (blockIdx.x * 1024 + t) >> 5;   // global warp id = candidate index
    int lane = t & 31;
    if (gw < cnt) {
        unsigned long long my = keys[gw];
        int cntR = (cnt + 31) & ~31;
        int greater = 0;
        for (int base = 0; base < cntR; base += 32) {
            unsigned long long k = keys[base + lane];
            greater += __popc(__ballot_sync(0xffffffffu, k > my));
        }
        if (lane == 0 && greater < MM) g_topKeys[greater] = my;
    }
}

// ---------------- k_decode: top-M box decode (parallel gather) -------------------
__global__ void k_decode(const float4* __restrict__ anchors,
                         const float4* __restrict__ deltas) {
    int m = blockIdx.x * blockDim.x + threadIdx.x;
    if (m == 0) g_candCount = 0;   // reset for next replay (all readers done)
    if (m >= MM) return;
    unsigned long long key = g_topKeys[m];
    bool valid = (key >> 32) != 0ULL;
    unsigned idx = 0xFFFFFFFFu - (unsigned)(key & 0xFFFFFFFFull);
    float4 a = valid ? __ldg(anchors + idx) : make_float4(0.f, 0.f, 0.f, 0.f);
    float4 d = valid ? __ldg(deltas + idx)  : make_float4(0.f, 0.f, 0.f, 0.f);
    float w  = a.z - a.x;
    float h  = a.w - a.y;
    float cx = a.x + 0.5f * w;
    float cy = a.y + 0.5f * h;
    float ncx = cx + d.x * w;
    float ncy = cy + d.y * h;
    float nw  = w * expf(d.z);
    float nh  = h * expf(d.w);
    float x1 = ncx - 0.5f * nw, y1 = ncy - 0.5f * nh;
    float x2 = ncx + 0.5f * nw, y2 = ncy + 0.5f * nh;
    x1 = fminf(fmaxf(x1, 0.f), 1024.f);
    y1 = fminf(fmaxf(y1, 0.f), 1024.f);
    x2 = fminf(fmaxf(x2, 0.f), 1024.f);
    y2 = fminf(fmaxf(y2, 0.f), 1024.f);
    bool big = ((x2 - x1) >= 1.0f) && ((y2 - y1) >= 1.0f);
    g_boxes[m] = make_float4(x1, y1, x2, y2);
    g_keep0[m] = (valid && big) ? 1 : 0;
}

// ---------------- k_pairs: upper-triangle IoU > 0.7 -> edge list -----------------
#define TB 64
__global__ void k_pairs() {
    int bx = blockIdx.x, by = blockIdx.y;
    if (by < bx) return;
    __shared__ float4 bi[TB], bj[TB];
    __shared__ float  ai[TB], aj[TB];
    __shared__ int    ki[TB], kj[TB];
    int t = threadIdx.x; // 256
    if (t < TB) {
        int i = bx * TB + t;
        if (i < MM) { float4 b = g_boxes[i]; bi[t] = b; ai[t] = (b.z - b.x) * (b.w - b.y); ki[t] = g_keep0[i]; }
        else ki[t] = 0;
        int j = by * TB + t;
        if (j < MM) { float4 b = g_boxes[j]; bj[t] = b; aj[t] = (b.z - b.x) * (b.w - b.y); kj[t] = g_keep0[j]; }
        else kj[t] = 0;
    }
    __syncthreads();
    for (int p = t; p < TB * TB; p += 256) {
        int li = p >> 6, lj = p & 63;
        int i = bx * TB + li, j = by * TB + lj;
        if (j <= i || j >= MM) continue;
        if (!ki[li] || !kj[lj]) continue;
        float4 A = bi[li], B = bj[lj];
        float ltx = fmaxf(A.x, B.x), lty = fmaxf(A.y, B.y);
        float rbx = fminf(A.z, B.z), rby = fminf(A.w, B.w);
        float iw = fmaxf(rbx - ltx, 0.f), ih = fmaxf(rby - lty, 0.f);
        float inter = iw * ih;
        float iou = inter / (ai[li] + aj[lj] - inter + 1e-9f);
        if (iou > 0.7f) {
            int pos = atomicAdd(&g_edgeCount, 1);
            if (pos < EDGE_MAX) g_edges[pos] = ((unsigned)i << 16) | (unsigned)j;
        }
    }
}

// ---------------- k_finalize: order edges, resolve greedy NMS, write out ---------
__global__ void k_finalize(float* __restrict__ out) {
    __shared__ unsigned char dead[MM];
    __shared__ unsigned se[EDGE_MAX]; // 16 KB
    int t = threadIdx.x; // 1024
    for (int m = t; m < MM; m += 1024) dead[m] = g_keep0[m] ? 0 : 1;
    int ec = g_edgeCount; if (ec > EDGE_MAX) ec = EDGE_MAX;
    for (int i = t; i < EDGE_MAX; i += 1024) se[i] = (i < ec) ? g_edges[i] : 0xFFFFFFFFu;
    __syncthreads();

    if (ec > 256) {
        for (int k = 2; k <= EDGE_MAX; k <<= 1) {
            for (int j = k >> 1; j > 0; j >>= 1) {
                for (int i = t; i < EDGE_MAX; i += 1024) {
                    int ixj = i ^ j;
                    if (ixj > i) {
                        unsigned a = se[i], b = se[ixj];
                        bool up = ((i & k) == 0);
                        if (up ? (a > b) : (a < b)) { se[i] = b; se[ixj] = a; }
                    }
                }
                __syncthreads();
            }
        }
    } else if (t == 0) {
        for (int a = 1; a < ec; a++) {
            unsigned key = se[a];
            int b = a - 1;
            while (b >= 0 && se[b] > key) { se[b + 1] = se[b]; b--; }
            se[b + 1] = key;
        }
    }
    __syncthreads();

    if (t == 0) {
        for (int e = 0; e < ec; e++) {
            unsigned u = se[e];
            int i = (int)(u >> 16), j = (int)(u & 0xFFFFu);
            if (!dead[i]) dead[j] = 1;
        }
    }
    __syncthreads();

    for (int m = t; m < MM; m += 1024) {
        bool keep = (dead[m] == 0);
        float4 b = g_boxes[m];
        out[m * 4 + 0] = keep ? b.x : 0.f;
        out[m * 4 + 1] = keep ? b.y : 0.f;
        out[m * 4 + 2] = keep ? b.z : 0.f;
        out[m * 4 + 3] = keep ? b.w : 0.f;
        out[MM * 4 + m] = keep ? 1.f : 0.f;
    }
}

// ---------------- launch ----------------
extern "C" void kernel_launch(void* const* d_in, const int* in_sizes, int n_in,
                              void* d_out, int out_size) {
    int si = 0;
    for (int i = 1; i < n_in; i++) if (in_sizes[i] < in_sizes[si]) si = i;
    int others[2], o = 0;
    for (int i = 0; i < n_in && o < 2; i++) if (i != si) others[o++] = i;

    const float4* anchors = (const float4*)d_in[others[0]];
    const float2* score   = (const float2*)d_in[si];
    const float4* deltas  = (const float4*)d_in[others[1]];
    int n  = in_sizes[si] / 2;
    int n4 = in_sizes[si] / 4;

    k_main<<<132, 1024>>>((const float4*)score, n4);
    k_scan<<<1, 1024>>>();
    k_fb<<<132, 256>>>(score, n);
    k_rank<<<CAND / 32, 1024>>>();
    k_decode<<<(MM + 255) / 256, 256>>>(anchors, deltas);
    dim3 pg((MM + TB - 1) / TB, (MM + TB - 1) / TB);
    k_pairs<<<pg, 256>>>();
    k_finalize<<<1, 1024>>>((float*)d_out);
}

// round 4
// speedup vs baseline: 2.1082x; 1.1196x over previous
#include <cuda_runtime.h>
#include <math.h>

#define MM 2000
#define NB 4096
#define CAND 4096
#define EDGE_MAX 4096
#define T_STATIC 0.99925f

// ---------------- device scratch (zero-initialized at module load) ----------------
__device__ int                g_candCount;   // speculative count (k_main)
__device__ int                g_cnt;         // final candidate count for k_rank
__device__ int                g_nValid;      // min(count, MM)
__device__ int                g_edgeCount;
__device__ unsigned long long g_cand[CAND];
__device__ float4             g_boxes[MM];
__device__ int                g_keep0[MM];
__device__ unsigned int       g_edges[EDGE_MAX];

// ---------------- k_main: pure streaming speculative compact ----------------
__global__ __launch_bounds__(1024) void k_main(const float4* __restrict__ s4, int n4) {
    int nthr = gridDim.x * blockDim.x;
    int tid  = blockIdx.x * blockDim.x + threadIdx.x;
    for (int i = tid; i < n4; i += 4 * nthr) {
        int i1 = i + nthr, i2 = i + 2 * nthr, i3 = i + 3 * nthr;
        bool b1 = i1 < n4, b2 = i2 < n4, b3 = i3 < n4;
        float4 a0 = s4[i];
        float4 a1, a2, a3;
        if (b1) a1 = s4[i1];
        if (b2) a2 = s4[i2];
        if (b3) a3 = s4[i3];
        #define EMIT(v, idx)                                                        \
            if ((v) > T_STATIC) {                                                   \
                int pos = atomicAdd(&g_candCount, 1);                               \
                if (pos < CAND)                                                     \
                    g_cand[pos] = ((unsigned long long)__float_as_uint(v) << 32) |  \
                                  (unsigned long long)(0xFFFFFFFFu - (idx));        \
            }
        EMIT(a0.y, 2u * (unsigned)i)
        EMIT(a0.w, 2u * (unsigned)i + 1u)
        if (b1) { EMIT(a1.y, 2u * (unsigned)i1) EMIT(a1.w, 2u * (unsigned)i1 + 1u) }
        if (b2) { EMIT(a2.y, 2u * (unsigned)i2) EMIT(a2.w, 2u * (unsigned)i2 + 1u) }
        if (b3) { EMIT(a3.y, 2u * (unsigned)i3) EMIT(a3.w, 2u * (unsigned)i3 + 1u) }
        #undef EMIT
    }
}

// ---------------- k_fb: validate speculation; exact re-selection if it failed ----
// Normal path: thread 0 publishes counts and exits (~no-op).
// Pathological path (static threshold missed): ONE block rebuilds an exact
// candidate set via shared histogram + cutoff + recompaction. Slow, never runs
// for sane inputs — correctness backstop only.
__global__ __launch_bounds__(1024) void k_fb(const float2* __restrict__ score, int n) {
    int t = threadIdx.x;
    __shared__ int s_fb;
    if (t == 0) {
        int c = g_candCount;
        s_fb = (c < MM || c > CAND);
        if (!s_fb) { g_cnt = c; g_nValid = MM; g_edgeCount = 0; }
    }
    __syncthreads();
    if (!s_fb) return;

    // ---- exact fallback ----
    __shared__ unsigned sh[NB];
    __shared__ unsigned s_cut;
    __shared__ int s_cnt2;
    for (int i = t; i < NB; i += 1024) sh[i] = 0u;
    __syncthreads();
    for (int i = t; i < n; i += 1024) {
        float v = score[i].y;
        if (v > 0.5f) {
            unsigned u = __float_as_uint(v);
            unsigned b = (u - 0x3F000000u) >> 11;
            if (b > NB - 1u) b = NB - 1u;
            atomicAdd(&sh[b], 1u);
        }
    }
    __syncthreads();
    if (t == 0) {
        unsigned run = 0; unsigned cut = 0;
        for (int b = NB - 1; b >= 0; b--) {
            run += sh[b];
            if (run >= (unsigned)MM) { cut = (unsigned)b; break; }
        }
        s_cut = cut;
        s_cnt2 = 0;
    }
    __syncthreads();
    unsigned cut = s_cut;
    for (int i = t; i < n; i += 1024) {
        float v = score[i].y;
        if (v > 0.5f) {
            unsigned u = __float_as_uint(v);
            unsigned b = (u - 0x3F000000u) >> 11;
            if (b > NB - 1u) b = NB - 1u;
            if (b >= cut) {
                int pos = atomicAdd(&s_cnt2, 1);
                if (pos < CAND)
                    g_cand[pos] = ((unsigned long long)u << 32) |
                                  (unsigned long long)(0xFFFFFFFFu - (unsigned)i);
            }
        }
    }
    __syncthreads();
    if (t == 0) {
        int c2 = s_cnt2; if (c2 > CAND) c2 = CAND;
        g_cnt = c2;
        g_nValid = (c2 < MM) ? c2 : MM;
        g_edgeCount = 0;
    }
}

// ---------------- k_rank: warp-per-candidate rank-by-count + fused decode --------
// rank(c) = #{keys > key_c}; keys distinct (index in low bits). Rank < MM warps
// decode their box straight into g_boxes/g_keep0 — no sort, no gather kernel.
__global__ __launch_bounds__(1024) void k_rank(const float4* __restrict__ anchors,
                                               const float4* __restrict__ deltas) {
    __shared__ unsigned long long keys[CAND]; // 32 KB
    int cnt = g_cnt;
    int t = threadIdx.x;
    if ((int)blockIdx.x * 32 >= cnt) return;   // no candidates in this block's range
    for (int i = t; i < CAND; i += 1024) keys[i] = (i < cnt) ? g_cand[i] : 0ULL;
    __syncthreads();
    int gw = (blockIdx.x * 1024 + t) >> 5;
    int lane = t & 31;
    if (gw >= cnt) return;
    unsigned long long my = keys[gw];
    int g = 0;
    for (int base = 0; base < CAND; base += 128) {
        unsigned long long k0 = keys[base       + lane];
        unsigned long long k1 = keys[base +  32 + lane];
        unsigned long long k2 = keys[base +  64 + lane];
        unsigned long long k3 = keys[base +  96 + lane];
        g += __popc(__ballot_sync(0xffffffffu, k0 > my));
        g += __popc(__ballot_sync(0xffffffffu, k1 > my));
        g += __popc(__ballot_sync(0xffffffffu, k2 > my));
        g += __popc(__ballot_sync(0xffffffffu, k3 > my));
    }
    if (lane == 0 && g < MM) {
        unsigned idx = 0xFFFFFFFFu - (unsigned)(my & 0xFFFFFFFFull);
        float4 a = __ldg(anchors + idx);
        float4 d = __ldg(deltas + idx);
        float w  = a.z - a.x;
        float h  = a.w - a.y;
        float cx = a.x + 0.5f * w;
        float cy = a.y + 0.5f * h;
        float ncx = cx + d.x * w;
        float ncy = cy + d.y * h;
        float nw  = w * expf(d.z);
        float nh  = h * expf(d.w);
        float x1 = ncx - 0.5f * nw, y1 = ncy - 0.5f * nh;
        float x2 = ncx + 0.5f * nw, y2 = ncy + 0.5f * nh;
        x1 = fminf(fmaxf(x1, 0.f), 1024.f);
        y1 = fminf(fmaxf(y1, 0.f), 1024.f);
        x2 = fminf(fmaxf(x2, 0.f), 1024.f);
        y2 = fminf(fmaxf(y2, 0.f), 1024.f);
        bool big = ((x2 - x1) >= 1.0f) && ((y2 - y1) >= 1.0f);
        g_boxes[g] = make_float4(x1, y1, x2, y2);
        g_keep0[g] = big ? 1 : 0;
    }
}

// ---------------- k_pairs: upper-triangle IoU > 0.7 -> edge list -----------------
#define TB 64
__global__ void k_pairs() {
    int bx = blockIdx.x, by = blockIdx.y;
    if (by < bx) return;
    __shared__ float4 bi[TB], bj[TB];
    __shared__ float  ai[TB], aj[TB];
    __shared__ int    ki[TB], kj[TB];
    int nV = g_nValid;
    int t = threadIdx.x; // 256
    if (t < TB) {
        int i = bx * TB + t;
        if (i < nV) { float4 b = g_boxes[i]; bi[t] = b; ai[t] = (b.z - b.x) * (b.w - b.y); ki[t] = g_keep0[i]; }
        else ki[t] = 0;
        int j = by * TB + t;
        if (j < nV) { float4 b = g_boxes[j]; bj[t] = b; aj[t] = (b.z - b.x) * (b.w - b.y); kj[t] = g_keep0[j]; }
        else kj[t] = 0;
    }
    __syncthreads();
    for (int p = t; p < TB * TB; p += 256) {
        int li = p >> 6, lj = p & 63;
        int i = bx * TB + li, j = by * TB + lj;
        if (j <= i) continue;
        if (!ki[li] || !kj[lj]) continue;
        float4 A = bi[li], B = bj[lj];
        float ltx = fmaxf(A.x, B.x), lty = fmaxf(A.y, B.y);
        float rbx = fminf(A.z, B.z), rby = fminf(A.w, B.w);
        float iw = fmaxf(rbx - ltx, 0.f), ih = fmaxf(rby - lty, 0.f);
        float inter = iw * ih;
        float iou = inter / (ai[li] + aj[lj] - inter + 1e-9f);
        if (iou > 0.7f) {
            int pos = atomicAdd(&g_edgeCount, 1);
            if (pos < EDGE_MAX) g_edges[pos] = ((unsigned)i << 16) | (unsigned)j;
        }
    }
}

// ---------------- k_finalize: order edges, resolve greedy NMS, write out ---------
__global__ void k_finalize(float* __restrict__ out) {
    __shared__ unsigned char dead[MM];
    __shared__ unsigned se[EDGE_MAX]; // 16 KB
    int t = threadIdx.x; // 1024
    int nV = g_nValid;
    for (int m = t; m < MM; m += 1024) dead[m] = (m < nV && g_keep0[m]) ? 0 : 1;
    int ec = g_edgeCount; if (ec > EDGE_MAX) ec = EDGE_MAX;
    for (int i = t; i < EDGE_MAX; i += 1024) se[i] = (i < ec) ? g_edges[i] : 0xFFFFFFFFu;
    __syncthreads();
    if (t == 0) g_candCount = 0;   // reset for next replay

    if (ec > 256) {
        for (int k = 2; k <= EDGE_MAX; k <<= 1) {
            for (int j = k >> 1; j > 0; j >>= 1) {
                for (int i = t; i < EDGE_MAX; i += 1024) {
                    int ixj = i ^ j;
                    if (ixj > i) {
                        unsigned a = se[i], b = se[ixj];
                        bool up = ((i & k) == 0);
                        if (up ? (a > b) : (a < b)) { se[i] = b; se[ixj] = a; }
                    }
                }
                __syncthreads();
            }
        }
    } else if (t == 0) {
        for (int a = 1; a < ec; a++) {
            unsigned key = se[a];
            int b = a - 1;
            while (b >= 0 && se[b] > key) { se[b + 1] = se[b]; b--; }
            se[b + 1] = key;
        }
    }
    __syncthreads();

    if (t == 0) {
        for (int e = 0; e < ec; e++) {
            unsigned u = se[e];
            int i = (int)(u >> 16), j = (int)(u & 0xFFFFu);
            if (!dead[i]) dead[j] = 1;
        }
    }
    __syncthreads();

    for (int m = t; m < MM; m += 1024) {
        bool keep = (dead[m] == 0);
        float4 b = g_boxes[m];
        out[m * 4 + 0] = keep ? b.x : 0.f;
        out[m * 4 + 1] = keep ? b.y : 0.f;
        out[m * 4 + 2] = keep ? b.z : 0.f;
        out[m * 4 + 3] = keep ? b.w : 0.f;
        out[MM * 4 + m] = keep ? 1.f : 0.f;
    }
}

// ---------------- launch ----------------
extern "C" void kernel_launch(void* const* d_in, const int* in_sizes, int n_in,
                              void* d_out, int out_size) {
    int si = 0;
    for (int i = 1; i < n_in; i++) if (in_sizes[i] < in_sizes[si]) si = i;
    int others[2], o = 0;
    for (int i = 0; i < n_in && o < 2; i++) if (i != si) others[o++] = i;

    const float4* anchors = (const float4*)d_in[others[0]];
    const float2* score   = (const float2*)d_in[si];
    const float4* deltas  = (const float4*)d_in[others[1]];
    int n  = in_sizes[si] / 2;
    int n4 = in_sizes[si] / 4;

    k_main<<<148, 1024>>>((const float4*)score, n4);
    k_fb<<<1, 1024>>>(score, n);
    k_rank<<<CAND / 32, 1024>>>(anchors, deltas);
    dim3 pg((MM + TB - 1) / TB, (MM + TB - 1) / TB);
    k_pairs<<<pg, 256>>>();
    k_finalize<<<1, 1024>>>((float*)d_out);
}

// round 5
// speedup vs baseline: 2.1311x; 1.0109x over previous
#include <cuda_runtime.h>
#include <math.h>

#define MM 2000
#define NB 4096
#define CAND 4096
#define EDGE_MAX 4096
#define T_STATIC 0.99925f
#define TB 32
#define NT ((MM + TB - 1) / TB)   // 63 tiles per dim

// ---------------- device scratch (zero-initialized at module load) ----------------
__device__ int                g_candCount;   // speculative count (k_main)
__device__ int                g_cnt;         // final candidate count for k_rank
__device__ int                g_nValid;      // min(count, MM)
__device__ int                g_edgeCount;
__device__ unsigned int      g_done1, g_done2;
__device__ unsigned long long g_cand[CAND];
__device__ float4             g_boxes[MM];
__device__ int                g_keep0[MM];
__device__ unsigned int       g_edges[EDGE_MAX];

// ---------------- k_main: streaming speculative compact + last-block validation --
__global__ __launch_bounds__(1024) void k_main(const float4* __restrict__ s4, int n4,
                                               const float2* __restrict__ score, int n) {
    int nthr = gridDim.x * blockDim.x;
    int tid  = blockIdx.x * blockDim.x + threadIdx.x;
    for (int i = tid; i < n4; i += 4 * nthr) {
        int i1 = i + nthr, i2 = i + 2 * nthr, i3 = i + 3 * nthr;
        bool b1 = i1 < n4, b2 = i2 < n4, b3 = i3 < n4;
        float4 a0 = s4[i];
        float4 a1, a2, a3;
        if (b1) a1 = s4[i1];
        if (b2) a2 = s4[i2];
        if (b3) a3 = s4[i3];
        #define EMIT(v, idx)                                                        \
            if ((v) > T_STATIC) {                                                   \
                int pos = atomicAdd(&g_candCount, 1);                               \
                if (pos < CAND)                                                     \
                    g_cand[pos] = ((unsigned long long)__float_as_uint(v) << 32) |  \
                                  (unsigned long long)(0xFFFFFFFFu - (idx));        \
            }
        EMIT(a0.y, 2u * (unsigned)i)
        EMIT(a0.w, 2u * (unsigned)i + 1u)
        if (b1) { EMIT(a1.y, 2u * (unsigned)i1) EMIT(a1.w, 2u * (unsigned)i1 + 1u) }
        if (b2) { EMIT(a2.y, 2u * (unsigned)i2) EMIT(a2.w, 2u * (unsigned)i2 + 1u) }
        if (b3) { EMIT(a3.y, 2u * (unsigned)i3) EMIT(a3.w, 2u * (unsigned)i3 + 1u) }
        #undef EMIT
    }

    // ---- last-finishing block runs validation (and exact fallback if needed) ----
    __shared__ int s_last;
    __syncthreads();
    if (threadIdx.x == 0) {
        __threadfence();
        unsigned d = atomicAdd(&g_done1, 1u);
        s_last = (d == gridDim.x - 1) ? 1 : 0;
    }
    __syncthreads();
    if (!s_last) return;

    int t = threadIdx.x;
    __shared__ int s_fb;
    if (t == 0) {
        g_done1 = 0;
        int c = g_candCount;
        s_fb = (c < MM || c > CAND);
        if (!s_fb) { g_cnt = c; g_nValid = MM; }
    }
    __syncthreads();
    if (!s_fb) return;

    // pathological fallback: exact histogram selection by this one block
    __shared__ unsigned sh[NB];
    __shared__ unsigned s_cut;
    __shared__ int s_cnt2;
    for (int i = t; i < NB; i += 1024) sh[i] = 0u;
    __syncthreads();
    for (int i = t; i < n; i += 1024) {
        float v = score[i].y;
        if (v > 0.5f) {
            unsigned u = __float_as_uint(v);
            unsigned b = (u - 0x3F000000u) >> 11;
            if (b > NB - 1u) b = NB - 1u;
            atomicAdd(&sh[b], 1u);
        }
    }
    __syncthreads();
    if (t == 0) {
        unsigned run = 0; unsigned cut = 0;
        for (int b = NB - 1; b >= 0; b--) {
            run += sh[b];
            if (run >= (unsigned)MM) { cut = (unsigned)b; break; }
        }
        s_cut = cut;
        s_cnt2 = 0;
    }
    __syncthreads();
    unsigned cut = s_cut;
    for (int i = t; i < n; i += 1024) {
        float v = score[i].y;
        if (v > 0.5f) {
            unsigned u = __float_as_uint(v);
            unsigned b = (u - 0x3F000000u) >> 11;
            if (b > NB - 1u) b = NB - 1u;
            if (b >= cut) {
                int pos = atomicAdd(&s_cnt2, 1);
                if (pos < CAND)
                    g_cand[pos] = ((unsigned long long)u << 32) |
                                  (unsigned long long)(0xFFFFFFFFu - (unsigned)i);
            }
        }
    }
    __syncthreads();
    if (t == 0) {
        int c2 = s_cnt2; if (c2 > CAND) c2 = CAND;
        g_cnt = c2;
        g_nValid = (c2 < MM) ? c2 : MM;
    }
}

// ---------------- k_rank: warp-per-candidate rank-by-count + fused decode --------
__global__ __launch_bounds__(1024) void k_rank(const float4* __restrict__ anchors,
                                               const float4* __restrict__ deltas) {
    __shared__ unsigned long long keys[CAND]; // 32 KB
    int cnt = g_cnt;
    int t = threadIdx.x;
    if ((int)blockIdx.x * 32 >= cnt) return;
    for (int i = t; i < CAND; i += 1024) keys[i] = (i < cnt) ? g_cand[i] : 0ULL;
    __syncthreads();
    int gw = (blockIdx.x * 1024 + t) >> 5;
    int lane = t & 31;
    if (gw >= cnt) return;
    unsigned long long my = keys[gw];
    int g = 0;
    for (int base = 0; base < CAND; base += 128) {
        unsigned long long k0 = keys[base       + lane];
        unsigned long long k1 = keys[base +  32 + lane];
        unsigned long long k2 = keys[base +  64 + lane];
        unsigned long long k3 = keys[base +  96 + lane];
        g += __popc(__ballot_sync(0xffffffffu, k0 > my));
        g += __popc(__ballot_sync(0xffffffffu, k1 > my));
        g += __popc(__ballot_sync(0xffffffffu, k2 > my));
        g += __popc(__ballot_sync(0xffffffffu, k3 > my));
    }
    if (lane == 0 && g < MM) {
        unsigned idx = 0xFFFFFFFFu - (unsigned)(my & 0xFFFFFFFFull);
        float4 a = __ldg(anchors + idx);
        float4 d = __ldg(deltas + idx);
        float w  = a.z - a.x;
        float h  = a.w - a.y;
        float cx = a.x + 0.5f * w;
        float cy = a.y + 0.5f * h;
        float ncx = cx + d.x * w;
        float ncy = cy + d.y * h;
        float nw  = w * expf(d.z);
        float nh  = h * expf(d.w);
        float x1 = ncx - 0.5f * nw, y1 = ncy - 0.5f * nh;
        float x2 = ncx + 0.5f * nw, y2 = ncy + 0.5f * nh;
        x1 = fminf(fmaxf(x1, 0.f), 1024.f);
        y1 = fminf(fmaxf(y1, 0.f), 1024.f);
        x2 = fminf(fmaxf(x2, 0.f), 1024.f);
        y2 = fminf(fmaxf(y2, 0.f), 1024.f);
        bool big = ((x2 - x1) >= 1.0f) && ((y2 - y1) >= 1.0f);
        g_boxes[g] = make_float4(x1, y1, x2, y2);
        g_keep0[g] = big ? 1 : 0;
    }
}

// ---------------- k_pairs: 32x32 tiles, reg i-box, 4 pairs/thread; last block
//                  runs the NMS finalize epilogue ------------------------------
__global__ __launch_bounds__(256) void k_pairs(float* __restrict__ out) {
    __shared__ float4 bj[TB];
    __shared__ float  aj[TB];
    __shared__ int    kj[TB];
    int bx = blockIdx.x, by = blockIdx.y;
    int t = threadIdx.x; // 256
    int nV = g_nValid;

    if (by >= bx) { // upper-triangle tiles do work; others just arrive
        if (t < TB) {
            int j = by * TB + t;
            if (j < nV) {
                float4 b = g_boxes[j];
                bj[t] = b; aj[t] = (b.z - b.x) * (b.w - b.y); kj[t] = g_keep0[j];
            } else kj[t] = 0;
        }
        __syncthreads();
        int li = t >> 3;               // 32 rows, 8 threads each
        int i  = bx * TB + li;
        if (i < nV && g_keep0[i]) {
            float4 A = g_boxes[i];     // L1-broadcast across the 8 threads of this row
            float ai = (A.z - A.x) * (A.w - A.y);
            int j0 = by * TB + (t & 7) * 4;
            #pragma unroll
            for (int u = 0; u < 4; u++) {
                int j = j0 + u;
                int lj = (t & 7) * 4 + u;
                if (j > i && kj[lj]) {
                    float4 B = bj[lj];
                    float ltx = fmaxf(A.x, B.x), lty = fmaxf(A.y, B.y);
                    float rbx = fminf(A.z, B.z), rby = fminf(A.w, B.w);
                    float iw = fmaxf(rbx - ltx, 0.f), ih = fmaxf(rby - lty, 0.f);
                    float inter = iw * ih;
                    float iou = inter / (ai + aj[lj] - inter + 1e-9f);
                    if (iou > 0.7f) {
                        int pos = atomicAdd(&g_edgeCount, 1);
                        if (pos < EDGE_MAX) g_edges[pos] = ((unsigned)i << 16) | (unsigned)j;
                    }
                }
            }
        }
    }

    // ---- last-finishing block runs finalize ----
    __shared__ int s_last;
    __syncthreads();
    if (t == 0) {
        __threadfence();
        unsigned d = atomicAdd(&g_done2, 1u);
        s_last = (d == gridDim.x * gridDim.y - 1) ? 1 : 0;
    }
    __syncthreads();
    if (!s_last) return;

    __shared__ unsigned char dead[MM];
    __shared__ unsigned se[EDGE_MAX]; // 16 KB
    for (int m = t; m < MM; m += 256) dead[m] = (m < nV && g_keep0[m]) ? 0 : 1;
    int ec = g_edgeCount; if (ec > EDGE_MAX) ec = EDGE_MAX;
    for (int i = t; i < EDGE_MAX; i += 256) se[i] = (i < ec) ? g_edges[i] : 0xFFFFFFFFu;
    __syncthreads();

    if (ec > 128) {
        for (int k = 2; k <= EDGE_MAX; k <<= 1) {
            for (int j = k >> 1; j > 0; j >>= 1) {
                for (int i = t; i < EDGE_MAX; i += 256) {
                    int ixj = i ^ j;
                    if (ixj > i) {
                        unsigned a = se[i], b = se[ixj];
                        bool up = ((i & k) == 0);
                        if (up ? (a > b) : (a < b)) { se[i] = b; se[ixj] = a; }
                    }
                }
                __syncthreads();
            }
        }
    } else if (t == 0) {
        for (int a = 1; a < ec; a++) {
            unsigned key = se[a];
            int b = a - 1;
            while (b >= 0 && se[b] > key) { se[b + 1] = se[b]; b--; }
            se[b + 1] = key;
        }
    }
    __syncthreads();

    if (t == 0) {
        for (int e = 0; e < ec; e++) {
            unsigned u = se[e];
            int i = (int)(u >> 16), j = (int)(u & 0xFFFFu);
            if (!dead[i]) dead[j] = 1;
        }
    }
    __syncthreads();

    for (int m = t; m < MM; m += 256) {
        bool keep = (dead[m] == 0);
        float4 b = g_boxes[m];
        out[m * 4 + 0] = keep ? b.x : 0.f;
        out[m * 4 + 1] = keep ? b.y : 0.f;
        out[m * 4 + 2] = keep ? b.z : 0.f;
        out[m * 4 + 3] = keep ? b.w : 0.f;
        out[MM * 4 + m] = keep ? 1.f : 0.f;
    }
    __syncthreads();
    if (t == 0) {   // reset state for next replay
        g_candCount = 0;
        g_edgeCount = 0;
        g_done2 = 0;
    }
}

// ---------------- launch ----------------
extern "C" void kernel_launch(void* const* d_in, const int* in_sizes, int n_in,
                              void* d_out, int out_size) {
    int si = 0;
    for (int i = 1; i < n_in; i++) if (in_sizes[i] < in_sizes[si]) si = i;
    int others[2], o = 0;
    for (int i = 0; i < n_in && o < 2; i++) if (i != si) others[o++] = i;

    const float4* anchors = (const float4*)d_in[others[0]];
    const float2* score   = (const float2*)d_in[si];
    const float4* deltas  = (const float4*)d_in[others[1]];
    int n  = in_sizes[si] / 2;
    int n4 = in_sizes[si] / 4;

    k_main<<<148, 1024>>>((const float4*)score, n4, score, n);
    k_rank<<<CAND / 32, 1024>>>(anchors, deltas);
    dim3 pg(NT, NT);
    k_pairs<<<pg, 256>>>((float*)d_out);
}